// round 8
// baseline (speedup 1.0000x reference)
#include <cuda_runtime.h>
#include <cstdint>

// Problem constants
#define NN 8
#define CC 128
#define HH 56
#define WW 56
#define COo 16
#define HWSZ (HH*WW)

// Conv tiling
#define S_SPLIT 8            // K-split over channels (blocks)
#define KC (CC/S_SPLIT)      // 16 channels per block
#define KCS 4                // channels per smem chunk
#define TH 8                 // output rows per block
#define TROWS (TH+8)         // input rows incl. halo (dilation 2 * (5-1) = 8)
#define TCOLS (WW+18)        // input cols incl. halo (dilation 3 * (7-1) = 18) = 74
#define TCSTRIDE 80          // padded col stride
#define THREADS_A 224        // 8 rows * 28 wgroups = 7 full warps

// Split-K scratch: [S][N][CO][H*W]
__device__ float g_ypart[S_SPLIT * NN * COo * HWSZ];

__device__ __forceinline__ unsigned long long pack2(float x) {
    unsigned long long r;
    unsigned int xi = __float_as_uint(x);
    asm("mov.b64 %0, {%1, %1};" : "=l"(r) : "r"(xi));
    return r;
}
__device__ __forceinline__ unsigned long long ffma2(unsigned long long a,
                                                    unsigned long long b,
                                                    unsigned long long c) {
    unsigned long long d;
    asm("fma.rn.f32x2 %0, %1, %2, %3;" : "=l"(d) : "l"(a), "l"(b), "l"(c));
    return d;
}
__device__ __forceinline__ void unpack2(unsigned long long v, float& lo, float& hi) {
    unsigned int l, h;
    asm("mov.b64 {%0, %1}, %2;" : "=r"(l), "=r"(h) : "l"(v));
    lo = __uint_as_float(l);
    hi = __uint_as_float(h);
}

// ---------------------------------------------------------------------------
// Kernel A: dilated 5x7 conv (C->CO), split-K over channel groups.
// out[n,o,h,w] += sum_{c in block's 16 channels} sum_{kh,kw}
//                  x[n,c,h-4+2kh, w-9+3kw] * w3[o,c,kh,kw]
// Each thread: 2 pixels (w, w+28) x 16 CO, accumulated as 16 f32x2 regs.
// ---------------------------------------------------------------------------
__global__ __launch_bounds__(THREADS_A)
void conv_partial_kernel(const float* __restrict__ x, const float* __restrict__ w3) {
    __shared__ float xs[KCS][TROWS][TCSTRIDE];
    __shared__ __align__(16) float ws[KCS][5][7][COo];   // [ci][kh][kw][o]

    const int ht = blockIdx.x;   // 0..6
    const int n  = blockIdx.y;   // 0..7
    const int s  = blockIdx.z;   // 0..7
    const int tid = threadIdx.x;
    const int r  = tid / 28;     // output row within tile, 0..7
    const int wg = tid % 28;     // first pixel column, 0..27 (second = wg+28)
    const int h0 = ht * TH;
    const int cbase = s * KC;

    unsigned long long acc0[8], acc1[8];
#pragma unroll
    for (int j = 0; j < 8; j++) { acc0[j] = 0ull; acc1[j] = 0ull; }

    for (int cc = 0; cc < KC; cc += KCS) {
        __syncthreads();  // protect smem reuse from previous chunk's readers

        // --- stage x tile: KCS channels x TROWS x TCOLS (zero-padded halo) ---
        for (int idx = tid; idx < KCS * TROWS * TCOLS; idx += THREADS_A) {
            int ci  = idx / (TROWS * TCOLS);
            int rem = idx % (TROWS * TCOLS);
            int tr  = rem / TCOLS;
            int tc  = rem % TCOLS;
            int h_in = h0 - 4 + tr;
            int w_in = tc - 9;
            float v = 0.0f;
            if ((unsigned)h_in < HH && (unsigned)w_in < WW)
                v = x[(((size_t)n * CC + (cbase + cc + ci)) * HH + h_in) * WW + w_in];
            xs[ci][tr][tc] = v;
        }
        // --- stage weights, transposed to [ci][kh][kw][o] so CO is contiguous ---
        for (int idx = tid; idx < KCS * 35 * COo; idx += THREADS_A) {
            int ci  = idx / (35 * COo);
            int rem = idx % (35 * COo);
            int t   = rem / COo;       // kh*7 + kw
            int o   = rem % COo;
            int c   = cbase + cc + ci;
            (&ws[0][0][0][0])[idx] = w3[((size_t)o * CC + c) * 35 + t];
        }
        __syncthreads();

        // --- compute ---
#pragma unroll
        for (int ci = 0; ci < KCS; ci++) {
#pragma unroll
            for (int kh = 0; kh < 5; kh++) {
                const float* xrow = &xs[ci][r + 2 * kh][0];
#pragma unroll
                for (int kw = 0; kw < 7; kw++) {
                    float xa = xrow[wg + 3 * kw];
                    float xb = xrow[wg + 28 + 3 * kw];
                    unsigned long long xa2 = pack2(xa);
                    unsigned long long xb2 = pack2(xb);
                    const ulonglong2* wp = (const ulonglong2*)&ws[ci][kh][kw][0];
#pragma unroll
                    for (int q = 0; q < 4; q++) {
                        ulonglong2 wv = wp[q];
                        acc0[2*q]   = ffma2(xa2, wv.x, acc0[2*q]);
                        acc0[2*q+1] = ffma2(xa2, wv.y, acc0[2*q+1]);
                        acc1[2*q]   = ffma2(xb2, wv.x, acc1[2*q]);
                        acc1[2*q+1] = ffma2(xb2, wv.y, acc1[2*q+1]);
                    }
                }
            }
        }
    }

    // --- store partials: g_ypart[s][n][o][h*56 + w] ---
    const int h = h0 + r;
    float* yp = &g_ypart[(((size_t)s * NN + n) * COo) * HWSZ + h * WW];
#pragma unroll
    for (int j = 0; j < 8; j++) {
        float lo, hi;
        unpack2(acc0[j], lo, hi);
        yp[(2*j)   * HWSZ + wg] = lo;
        yp[(2*j+1) * HWSZ + wg] = hi;
        unpack2(acc1[j], lo, hi);
        yp[(2*j)   * HWSZ + wg + 28] = lo;
        yp[(2*j+1) * HWSZ + wg + 28] = hi;
    }
}

// ---------------------------------------------------------------------------
// Kernel B: reduce split-K partials, apply w4 (16x16) then w5 (128x16), store.
// One thread per output pixel; 4 rows x 56 cols per block (224 threads).
// ---------------------------------------------------------------------------
__global__ __launch_bounds__(THREADS_A)
void epilogue_kernel(const float* __restrict__ w4, const float* __restrict__ w5,
                     float* __restrict__ out) {
    __shared__ float w4s[COo * COo];
    __shared__ float w5s[CC * COo];
    const int tid = threadIdx.x;
    for (int i = tid; i < COo * COo; i += THREADS_A) w4s[i] = w4[i];
    for (int i = tid; i < CC * COo; i += THREADS_A) w5s[i] = w5[i];
    __syncthreads();

    const int n = blockIdx.y;
    const int h = blockIdx.x * 4 + tid / WW;
    const int w = tid % WW;
    const int p = h * WW + w;

    float y[COo];
#pragma unroll
    for (int c = 0; c < COo; c++) {
        float v = 0.0f;
#pragma unroll
        for (int s = 0; s < S_SPLIT; s++)
            v += g_ypart[(((size_t)s * NN + n) * COo + c) * HWSZ + p];
        y[c] = v;
    }

    float z[COo];
#pragma unroll
    for (int j = 0; j < COo; j++) {
        float v = 0.0f;
#pragma unroll
        for (int c = 0; c < COo; c++) v += w4s[j * COo + c] * y[c];
        z[j] = v;
    }

    float* outp = out + ((size_t)n * CC) * HWSZ + p;
#pragma unroll 8
    for (int o = 0; o < CC; o++) {
        float v = 0.0f;
#pragma unroll
        for (int j = 0; j < COo; j++) v += w5s[o * COo + j] * z[j];
        outp[(size_t)o * HWSZ] = v;
    }
}

// ---------------------------------------------------------------------------
extern "C" void kernel_launch(void* const* d_in, const int* in_sizes, int n_in,
                              void* d_out, int out_size) {
    const float* x  = (const float*)d_in[0];
    const float* w3 = (const float*)d_in[1];
    const float* w4 = (const float*)d_in[2];
    const float* w5 = (const float*)d_in[3];
    float* out = (float*)d_out;

    dim3 gridA(HH / TH, NN, S_SPLIT);       // 7 x 8 x 8 = 448 blocks
    conv_partial_kernel<<<gridA, THREADS_A>>>(x, w3);

    dim3 gridB(HH / 4, NN);                 // 14 x 8 = 112 blocks
    epilogue_kernel<<<gridB, THREADS_A>>>(w4, w5, out);
}

// round 9
// speedup vs baseline: 1.0022x; 1.0022x over previous
#include <cuda_runtime.h>
#include <cstdint>

// Problem constants
#define NN 8
#define CC 128
#define HH 56
#define WW 56
#define COo 16
#define HWSZ (HH*WW)

// Conv tiling
#define S_SPLIT 8            // K-split over channels (blocks)
#define KC (CC/S_SPLIT)      // 16 channels per block
#define KCS 4                // channels per smem chunk
#define TH 8                 // output rows per block
#define TROWS (TH+8)         // input rows incl. halo (dilation 2 * (5-1) = 8)
#define TCOLS (WW+18)        // input cols incl. halo (dilation 3 * (7-1) = 18) = 74
#define TCSTRIDE 80          // padded col stride
#define THREADS_A 224        // 8 rows * 28 wgroups = 7 full warps

// Split-K scratch: [S][N][CO][H*W]
__device__ float g_ypart[S_SPLIT * NN * COo * HWSZ];

__device__ __forceinline__ unsigned long long pack2(float x) {
    unsigned long long r;
    unsigned int xi = __float_as_uint(x);
    asm("mov.b64 %0, {%1, %1};" : "=l"(r) : "r"(xi));
    return r;
}
__device__ __forceinline__ unsigned long long ffma2(unsigned long long a,
                                                    unsigned long long b,
                                                    unsigned long long c) {
    unsigned long long d;
    asm("fma.rn.f32x2 %0, %1, %2, %3;" : "=l"(d) : "l"(a), "l"(b), "l"(c));
    return d;
}
__device__ __forceinline__ void unpack2(unsigned long long v, float& lo, float& hi) {
    unsigned int l, h;
    asm("mov.b64 {%0, %1}, %2;" : "=r"(l), "=r"(h) : "l"(v));
    lo = __uint_as_float(l);
    hi = __uint_as_float(h);
}

// ---------------------------------------------------------------------------
// Kernel A: dilated 5x7 conv (C->CO), split-K over channel groups.
// out[n,o,h,w] += sum_{c in block's 16 channels} sum_{kh,kw}
//                  x[n,c,h-4+2kh, w-9+3kw] * w3[o,c,kh,kw]
// Each thread: 2 pixels (w, w+28) x 16 CO, accumulated as 16 f32x2 regs.
// ---------------------------------------------------------------------------
__global__ __launch_bounds__(THREADS_A)
void conv_partial_kernel(const float* __restrict__ x, const float* __restrict__ w3) {
    __shared__ float xs[KCS][TROWS][TCSTRIDE];
    __shared__ __align__(16) float ws[KCS][5][7][COo];   // [ci][kh][kw][o]

    const int ht = blockIdx.x;   // 0..6
    const int n  = blockIdx.y;   // 0..7
    const int s  = blockIdx.z;   // 0..7
    const int tid = threadIdx.x;
    const int r  = tid / 28;     // output row within tile, 0..7
    const int wg = tid % 28;     // first pixel column, 0..27 (second = wg+28)
    const int h0 = ht * TH;
    const int cbase = s * KC;

    unsigned long long acc0[8], acc1[8];
#pragma unroll
    for (int j = 0; j < 8; j++) { acc0[j] = 0ull; acc1[j] = 0ull; }

    for (int cc = 0; cc < KC; cc += KCS) {
        __syncthreads();  // protect smem reuse from previous chunk's readers

        // --- stage x tile: KCS channels x TROWS x TCOLS (zero-padded halo) ---
        for (int idx = tid; idx < KCS * TROWS * TCOLS; idx += THREADS_A) {
            int ci  = idx / (TROWS * TCOLS);
            int rem = idx % (TROWS * TCOLS);
            int tr  = rem / TCOLS;
            int tc  = rem % TCOLS;
            int h_in = h0 - 4 + tr;
            int w_in = tc - 9;
            float v = 0.0f;
            if ((unsigned)h_in < HH && (unsigned)w_in < WW)
                v = x[(((size_t)n * CC + (cbase + cc + ci)) * HH + h_in) * WW + w_in];
            xs[ci][tr][tc] = v;
        }
        // --- stage weights, transposed to [ci][kh][kw][o] so CO is contiguous ---
        for (int idx = tid; idx < KCS * 35 * COo; idx += THREADS_A) {
            int ci  = idx / (35 * COo);
            int rem = idx % (35 * COo);
            int t   = rem / COo;       // kh*7 + kw
            int o   = rem % COo;
            int c   = cbase + cc + ci;
            (&ws[0][0][0][0])[idx] = w3[((size_t)o * CC + c) * 35 + t];
        }
        __syncthreads();

        // --- compute ---
#pragma unroll
        for (int ci = 0; ci < KCS; ci++) {
#pragma unroll
            for (int kh = 0; kh < 5; kh++) {
                const float* xrow = &xs[ci][r + 2 * kh][0];
#pragma unroll
                for (int kw = 0; kw < 7; kw++) {
                    float xa = xrow[wg + 3 * kw];
                    float xb = xrow[wg + 28 + 3 * kw];
                    unsigned long long xa2 = pack2(xa);
                    unsigned long long xb2 = pack2(xb);
                    const ulonglong2* wp = (const ulonglong2*)&ws[ci][kh][kw][0];
#pragma unroll
                    for (int q = 0; q < 4; q++) {
                        ulonglong2 wv = wp[q];
                        acc0[2*q]   = ffma2(xa2, wv.x, acc0[2*q]);
                        acc0[2*q+1] = ffma2(xa2, wv.y, acc0[2*q+1]);
                        acc1[2*q]   = ffma2(xb2, wv.x, acc1[2*q]);
                        acc1[2*q+1] = ffma2(xb2, wv.y, acc1[2*q+1]);
                    }
                }
            }
        }
    }

    // --- store partials: g_ypart[s][n][o][h*56 + w] ---
    const int h = h0 + r;
    float* yp = &g_ypart[(((size_t)s * NN + n) * COo) * HWSZ + h * WW];
#pragma unroll
    for (int j = 0; j < 8; j++) {
        float lo, hi;
        unpack2(acc0[j], lo, hi);
        yp[(2*j)   * HWSZ + wg] = lo;
        yp[(2*j+1) * HWSZ + wg] = hi;
        unpack2(acc1[j], lo, hi);
        yp[(2*j)   * HWSZ + wg + 28] = lo;
        yp[(2*j+1) * HWSZ + wg + 28] = hi;
    }
}

// ---------------------------------------------------------------------------
// Kernel B: reduce split-K partials, apply w4 (16x16) then w5 (128x16), store.
// One thread per output pixel; 4 rows x 56 cols per block (224 threads).
// ---------------------------------------------------------------------------
__global__ __launch_bounds__(THREADS_A)
void epilogue_kernel(const float* __restrict__ w4, const float* __restrict__ w5,
                     float* __restrict__ out) {
    __shared__ float w4s[COo * COo];
    __shared__ float w5s[CC * COo];
    const int tid = threadIdx.x;
    for (int i = tid; i < COo * COo; i += THREADS_A) w4s[i] = w4[i];
    for (int i = tid; i < CC * COo; i += THREADS_A) w5s[i] = w5[i];
    __syncthreads();

    const int n = blockIdx.y;
    const int h = blockIdx.x * 4 + tid / WW;
    const int w = tid % WW;
    const int p = h * WW + w;

    float y[COo];
#pragma unroll
    for (int c = 0; c < COo; c++) {
        float v = 0.0f;
#pragma unroll
        for (int s = 0; s < S_SPLIT; s++)
            v += g_ypart[(((size_t)s * NN + n) * COo + c) * HWSZ + p];
        y[c] = v;
    }

    float z[COo];
#pragma unroll
    for (int j = 0; j < COo; j++) {
        float v = 0.0f;
#pragma unroll
        for (int c = 0; c < COo; c++) v += w4s[j * COo + c] * y[c];
        z[j] = v;
    }

    float* outp = out + ((size_t)n * CC) * HWSZ + p;
#pragma unroll 8
    for (int o = 0; o < CC; o++) {
        float v = 0.0f;
#pragma unroll
        for (int j = 0; j < COo; j++) v += w5s[o * COo + j] * z[j];
        outp[(size_t)o * HWSZ] = v;
    }
}

// ---------------------------------------------------------------------------
extern "C" void kernel_launch(void* const* d_in, const int* in_sizes, int n_in,
                              void* d_out, int out_size) {
    const float* x  = (const float*)d_in[0];
    const float* w3 = (const float*)d_in[1];
    const float* w4 = (const float*)d_in[2];
    const float* w5 = (const float*)d_in[3];
    float* out = (float*)d_out;

    dim3 gridA(HH / TH, NN, S_SPLIT);       // 7 x 8 x 8 = 448 blocks
    conv_partial_kernel<<<gridA, THREADS_A>>>(x, w3);

    dim3 gridB(HH / 4, NN);                 // 14 x 8 = 112 blocks
    epilogue_kernel<<<gridB, THREADS_A>>>(w4, w5, out);
}

// round 10
// speedup vs baseline: 1.0893x; 1.0869x over previous
#include <cuda_runtime.h>
#include <cstdint>

// Problem constants
#define NN 8
#define CC 128
#define HH 56
#define WW 56
#define COo 16
#define HWSZ (HH*WW)

// Conv tiling
#define S_SPLIT 16           // K-split over channels (16 tiles of 8 channels)
#define KC (CC/S_SPLIT)      // 8 channels per tile
#define KCS 4                // channels per smem chunk
#define TH 8                 // output rows per tile
#define TROWS (TH+8)         // input rows incl. halo (dilation 2 * (5-1) = 8)
#define TCOLS (WW+18)        // input cols incl. halo (dilation 3 * (7-1) = 18) = 74
#define TCSTRIDE 92          // 92 % 32 == 28 -> warp-spanning lanes hit disjoint banks
#define THREADS_A 224        // 8 rows * 28 wgroups = 7 full warps
#define NTILES (7*NN*S_SPLIT) // 896 tiles
#define GRID_A 444           // 148 SMs * 3 blocks: exactly one wave

// Split-K scratch: [S][N][CO][H*W]  (25.7 MB)
__device__ float g_ypart[S_SPLIT * NN * COo * HWSZ];
__device__ unsigned g_ctr;   // dynamic tile counter

__device__ __forceinline__ unsigned long long pack2(float x) {
    unsigned long long r;
    unsigned int xi = __float_as_uint(x);
    asm("mov.b64 %0, {%1, %1};" : "=l"(r) : "r"(xi));
    return r;
}
__device__ __forceinline__ unsigned long long ffma2(unsigned long long a,
                                                    unsigned long long b,
                                                    unsigned long long c) {
    unsigned long long d;
    asm("fma.rn.f32x2 %0, %1, %2, %3;" : "=l"(d) : "l"(a), "l"(b), "l"(c));
    return d;
}
__device__ __forceinline__ void unpack2(unsigned long long v, float& lo, float& hi) {
    unsigned int l, h;
    asm("mov.b64 {%0, %1}, %2;" : "=r"(l), "=r"(h) : "l"(v));
    lo = __uint_as_float(l);
    hi = __uint_as_float(h);
}

// ---------------------------------------------------------------------------
// Init kernel: reset the dynamic tile counter each replay (graph-safe).
// ---------------------------------------------------------------------------
__global__ void init_kernel() { g_ctr = GRID_A; }

// ---------------------------------------------------------------------------
// Kernel A: dilated 5x7 conv (C->CO), split-K over 16 channel groups.
// Persistent blocks (444 = one full wave at occ 3) pull tiles dynamically
// from g_ctr, eliminating the 4-block tail wave of the static 448 grid.
// Each thread: 2 pixels (w, w+28) x 16 CO, accumulated as 16 f32x2 regs.
// ---------------------------------------------------------------------------
__global__ __launch_bounds__(THREADS_A, 3)
void conv_partial_kernel(const float* __restrict__ x, const float* __restrict__ w3) {
    __shared__ float xs[KCS][TROWS][TCSTRIDE];
    __shared__ __align__(16) float ws[KCS][5][7][COo];   // [ci][kh][kw][o]
    __shared__ unsigned s_next;

    const int tid = threadIdx.x;
    const int r  = tid / 28;     // output row within tile, 0..7
    const int wg = tid % 28;     // first pixel column, 0..27 (second = wg+28)

    unsigned tile = blockIdx.x;

    while (tile < NTILES) {
        // tile -> (ht fastest for x L2 locality, then n, then s)
        const int ht = tile % 7;
        const int n  = (tile / 7) & (NN - 1);
        const int s  = tile / (7 * NN);
        const int h0 = ht * TH;
        const int cbase = s * KC;

        unsigned long long acc0[8], acc1[8];
#pragma unroll
        for (int j = 0; j < 8; j++) { acc0[j] = 0ull; acc1[j] = 0ull; }

#pragma unroll
        for (int cc = 0; cc < KC; cc += KCS) {
            __syncthreads();  // protect smem reuse from previous chunk's readers

            // --- stage x tile: KCS channels x TROWS x TCOLS (zero-padded halo) ---
            for (int idx = tid; idx < KCS * TROWS * TCOLS; idx += THREADS_A) {
                int ci  = idx / (TROWS * TCOLS);
                int rem = idx % (TROWS * TCOLS);
                int tr  = rem / TCOLS;
                int tc  = rem % TCOLS;
                int h_in = h0 - 4 + tr;
                int w_in = tc - 9;
                float v = 0.0f;
                if ((unsigned)h_in < HH && (unsigned)w_in < WW)
                    v = x[(((size_t)n * CC + (cbase + cc + ci)) * HH + h_in) * WW + w_in];
                xs[ci][tr][tc] = v;
            }
            // --- stage weights, transposed to [ci][kh][kw][o] so CO is contiguous ---
            for (int idx = tid; idx < KCS * 35 * COo; idx += THREADS_A) {
                int ci  = idx / (35 * COo);
                int rem = idx % (35 * COo);
                int t   = rem / COo;       // kh*7 + kw
                int o   = rem % COo;
                int c   = cbase + cc + ci;
                (&ws[0][0][0][0])[idx] = w3[((size_t)o * CC + c) * 35 + t];
            }
            __syncthreads();

            // --- compute ---
#pragma unroll
            for (int ci = 0; ci < KCS; ci++) {
#pragma unroll
                for (int kh = 0; kh < 5; kh++) {
                    const float* xrow = &xs[ci][r + 2 * kh][0];
#pragma unroll
                    for (int kw = 0; kw < 7; kw++) {
                        float xa = xrow[wg + 3 * kw];
                        float xb = xrow[wg + 28 + 3 * kw];
                        unsigned long long xa2 = pack2(xa);
                        unsigned long long xb2 = pack2(xb);
                        const ulonglong2* wp = (const ulonglong2*)&ws[ci][kh][kw][0];
#pragma unroll
                        for (int q = 0; q < 4; q++) {
                            ulonglong2 wv = wp[q];
                            acc0[2*q]   = ffma2(xa2, wv.x, acc0[2*q]);
                            acc0[2*q+1] = ffma2(xa2, wv.y, acc0[2*q+1]);
                            acc1[2*q]   = ffma2(xb2, wv.x, acc1[2*q]);
                            acc1[2*q+1] = ffma2(xb2, wv.y, acc1[2*q+1]);
                        }
                    }
                }
            }
        }

        // --- store partials: g_ypart[s][n][o][h*56 + w] ---
        const int h = h0 + r;
        float* yp = &g_ypart[(((size_t)s * NN + n) * COo) * HWSZ + h * WW];
#pragma unroll
        for (int j = 0; j < 8; j++) {
            float lo, hi;
            unpack2(acc0[j], lo, hi);
            yp[(2*j)   * HWSZ + wg] = lo;
            yp[(2*j+1) * HWSZ + wg] = hi;
            unpack2(acc1[j], lo, hi);
            yp[(2*j)   * HWSZ + wg + 28] = lo;
            yp[(2*j+1) * HWSZ + wg + 28] = hi;
        }

        // --- fetch next tile (dynamic balancing) ---
        __syncthreads();   // all threads done reading s_next from prior round
        if (tid == 0) s_next = atomicAdd(&g_ctr, 1u);
        __syncthreads();
        tile = s_next;
    }
}

// ---------------------------------------------------------------------------
// Kernel B: reduce 16 split-K partials, apply w4 (16x16) then w5 (128x16).
// 448 blocks (one per (row, n)); 4 threads per pixel: each reduces 4 of the
// 16 s-partials into smem, then handles 32 of the 128 output channels.
// ---------------------------------------------------------------------------
__global__ __launch_bounds__(THREADS_A)
void epilogue_kernel(const float* __restrict__ w4, const float* __restrict__ w5,
                     float* __restrict__ out) {
    __shared__ float w4s[COo * COo];
    __shared__ float w5s[CC * COo];
    __shared__ float ysh[COo][4][57];   // [c][q][px], pad 57 to soften conflicts
    const int tid = threadIdx.x;
    for (int i = tid; i < COo * COo; i += THREADS_A) w4s[i] = w4[i];
    for (int i = tid; i < CC * COo; i += THREADS_A) w5s[i] = w5[i];

    const int n  = blockIdx.y;
    const int h  = blockIdx.x;
    const int px = tid % 56;
    const int q  = tid / 56;          // 0..3
    const int p  = h * WW + px;
    __syncthreads();

    // partial reduction: each thread sums 4 of the 16 s-slices for all 16 c
#pragma unroll
    for (int c = 0; c < COo; c++) {
        float v = 0.0f;
#pragma unroll
        for (int ss = 0; ss < 4; ss++) {
            int s = q * 4 + ss;
            v += g_ypart[(((size_t)s * NN + n) * COo + c) * HWSZ + p];
        }
        ysh[c][q][px] = v;
    }
    __syncthreads();

    float y[COo];
#pragma unroll
    for (int c = 0; c < COo; c++)
        y[c] = ysh[c][0][px] + ysh[c][1][px] + ysh[c][2][px] + ysh[c][3][px];

    float z[COo];
#pragma unroll
    for (int j = 0; j < COo; j++) {
        float v = 0.0f;
#pragma unroll
        for (int c = 0; c < COo; c++) v += w4s[j * COo + c] * y[c];
        z[j] = v;
    }

    float* outp = out + ((size_t)n * CC) * HWSZ + p;
#pragma unroll 4
    for (int oo = 0; oo < 32; oo++) {
        int o = q * 32 + oo;
        float v = 0.0f;
#pragma unroll
        for (int j = 0; j < COo; j++) v += w5s[o * COo + j] * z[j];
        outp[(size_t)o * HWSZ] = v;
    }
}

// ---------------------------------------------------------------------------
extern "C" void kernel_launch(void* const* d_in, const int* in_sizes, int n_in,
                              void* d_out, int out_size) {
    const float* x  = (const float*)d_in[0];
    const float* w3 = (const float*)d_in[1];
    const float* w4 = (const float*)d_in[2];
    const float* w5 = (const float*)d_in[3];
    float* out = (float*)d_out;

    init_kernel<<<1, 1>>>();                            // reset tile counter
    conv_partial_kernel<<<GRID_A, THREADS_A>>>(x, w3);  // 444 persistent blocks
    dim3 gridB(HH, NN);                                 // 56 x 8 = 448 blocks
    epilogue_kernel<<<gridB, THREADS_A>>>(w4, w5, out);
}